// round 5
// baseline (speedup 1.0000x reference)
#include <cuda_runtime.h>

#define CH 6
#define MODES 16
#define BB 32
#define NPT 65536
#define NMASK 65535
#define TSTEPS 8

#define TILE 1024
#define HALO 4
#define EXT (TILE + 2*HALO)      // 1032
#define RKTHREADS 512            // 2 points per thread
#define EDG 516                  // per-channel stride in edge arrays (RKTHREADS+4)
#define FBLK 8                   // blocks per (b,i) in forward DFT

// -------- scratch (no allocations allowed) --------
__device__ float g_bufA[BB*CH*NPT];
__device__ float g_bufB[BB*CH*NPT];
__device__ float g_part[BB*CH*FBLK*MODES*2];
__device__ float g_Z[BB*CH*MODES*2];

__constant__ float c_w[CH*CH*3];   // [co][ci][3]
__constant__ float c_b[CH];

__device__ __forceinline__ float htanh(float x){
    float y;
    asm("tanh.approx.f32 %0, %1;" : "=f"(y) : "f"(x));
    return y;
}

// ---------------- RK4 step kernel ----------------
// 2 points/thread: thread t owns p1=2t+1, p2=2t+2; window [2t, 2t+3].
// Linearity split: conv(u + c*k) = conv(u) + c*conv(k); cu = conv(u) in regs.
// Edge arrays (double-buffered, stride-1, conflict-free), 1 barrier/stage:
//   eL[i] = k(2i)   (thread t writes i=t+1 <- kr[1]; reads i=t; i=0 sentinel)
//   eR[i] = k(2i+1) (thread t writes i=t <- kr[0]; reads i=t+1;
//                    i=RKTHREADS <- tail k(1025))
// Tail positions [1025,1031) handled by tid<6 via kt (full u+ck path on smem).
// Validity shrinks 1/side/stage; combine uses central [4, 1028) only.

template<int S>
__device__ __forceinline__ void stage(
    float (&cu)[CH][2],
    const float* __restrict__ eLr, const float* __restrict__ eRr,
    const float* __restrict__ ktr,
    float* __restrict__ eLw, float* __restrict__ eRw, float* __restrict__ ktw,
    const float* __restrict__ su,
    float cc, float aw, int gofs, int tid, bool edge,
    float (&kr)[CH][2], float (&acc)[CH][2], float (&acct)[CH])
{
    const int p0 = 2*tid;
    float a[CH][2];
    #pragma unroll
    for (int co=0; co<CH; co++){ a[co][0]=0.f; a[co][1]=0.f; }

    if (S == 0){
        // a = conv(u); u window from smem (already masked at load)
        #pragma unroll
        for (int ci=0; ci<CH; ci++){
            const float* ru = su + ci*EXT + p0;
            float2 u0 = *(const float2*)ru;        // p0, p0+1   (8B aligned)
            float2 u1 = *(const float2*)(ru + 2);  // p0+2, p0+3
            float xv[4] = {u0.x, u0.y, u1.x, u1.y};
            #pragma unroll
            for (int co=0; co<CH; co++){
                const float w0 = c_w[(co*CH+ci)*3 + 0];
                const float w1 = c_w[(co*CH+ci)*3 + 1];
                const float w2 = c_w[(co*CH+ci)*3 + 2];
                #pragma unroll
                for (int j=0; j<2; j++)
                    a[co][j] = fmaf(w0, xv[j], fmaf(w1, xv[j+1], fmaf(w2, xv[j+2], a[co][j])));
            }
        }
        #pragma unroll
        for (int co=0; co<CH; co++){ cu[co][0]=a[co][0]; cu[co][1]=a[co][1]; }
    } else {
        // a = cu + cc * conv(k)
        #pragma unroll
        for (int ci=0; ci<CH; ci++){
            float xvk[4];
            xvk[0] = eLr[ci*EDG + tid];
            xvk[1] = kr[ci][0];
            xvk[2] = kr[ci][1];
            xvk[3] = eRr[ci*EDG + tid + 1];
            if (edge){
                #pragma unroll
                for (int j=0; j<4; j++)
                    if ((unsigned)(gofs + p0 + j) >= NPT) xvk[j] = 0.f;
            }
            #pragma unroll
            for (int co=0; co<CH; co++){
                const float w0 = c_w[(co*CH+ci)*3 + 0];
                const float w1 = c_w[(co*CH+ci)*3 + 1];
                const float w2 = c_w[(co*CH+ci)*3 + 2];
                #pragma unroll
                for (int j=0; j<2; j++)
                    a[co][j] = fmaf(w0, xvk[j], fmaf(w1, xvk[j+1], fmaf(w2, xvk[j+2], a[co][j])));
            }
        }
        #pragma unroll
        for (int co=0; co<CH; co++){
            a[co][0] = fmaf(cc, a[co][0], cu[co][0]);
            a[co][1] = fmaf(cc, a[co][1], cu[co][1]);
        }
    }

    // tail point p = 1025+tid for tid<6 (full u + cc*k path via smem)
    float ttail[CH];
    if (tid < 6){
        const int p = TILE + 1 + tid;
        #pragma unroll
        for (int co=0; co<CH; co++) ttail[co] = 0.f;
        #pragma unroll
        for (int ci=0; ci<CH; ci++){
            float vv[3];
            #pragma unroll
            for (int t3=0; t3<3; t3++){
                int pp = p - 1 + t3;                 // 1024..1031
                float v = su[ci*EXT + pp];
                if (S > 0){
                    float kv = (pp == TILE) ? eLr[ci*EDG + RKTHREADS]
                                            : ktr[ci*8 + (pp - (TILE+1))];
                    v = fmaf(cc, kv, v);
                }
                if ((unsigned)(gofs + pp) >= NPT) v = 0.f;
                vv[t3] = v;
            }
            #pragma unroll
            for (int co=0; co<CH; co++){
                const float w0 = c_w[(co*CH+ci)*3 + 0];
                const float w1 = c_w[(co*CH+ci)*3 + 1];
                const float w2 = c_w[(co*CH+ci)*3 + 2];
                ttail[co] = fmaf(w0, vv[0], fmaf(w1, vv[1], fmaf(w2, vv[2], ttail[co])));
            }
        }
    }

    #pragma unroll
    for (int co=0; co<CH; co++){
        const float bias = c_b[co];
        #pragma unroll
        for (int j=0; j<2; j++){
            float t = htanh(a[co][j] + bias);
            kr[co][j] = t;
            acc[co][j] = fmaf(aw, t, acc[co][j]);
        }
        if (S < 3){
            eLw[co*EDG + tid + 1] = kr[co][1];   // k(2t+2)
            eRw[co*EDG + tid]     = kr[co][0];   // k(2t+1)
        }
    }
    if (tid < 6){
        #pragma unroll
        for (int co=0; co<CH; co++){
            float t = htanh(ttail[co] + c_b[co]);
            if (S < 3){
                ktw[co*8 + tid] = t;
                if (tid == 0) eRw[co*EDG + RKTHREADS] = t;   // k(1025)
            }
            if (tid < 3) acct[co] = fmaf(aw, t, acct[co]);
        }
    }
    if (S < 3) __syncthreads();
}

__global__ void __launch_bounds__(RKTHREADS, 2)
rk4_kernel(const float* __restrict__ src, float* __restrict__ dst,
           const float* __restrict__ t_span, int step)
{
    extern __shared__ float sm[];
    float* s_su = sm;                      // CH*EXT = 6192
    float* s_eL = s_su + CH*EXT;           // 2*CH*EDG
    float* s_eR = s_eL + 2*CH*EDG;         // 2*CH*EDG
    float* s_kt = s_eR + 2*CH*EDG;         // 2*CH*8

    const int b     = blockIdx.y;
    const int tile0 = blockIdx.x * TILE;
    const int gofs  = tile0 - HALO;
    const int tid   = threadIdx.x;
    const bool edge = (blockIdx.x == 0) | (blockIdx.x == gridDim.x - 1);
    const float dt  = t_span[step+1] - t_span[step];

    if (tid < CH){
        s_eL[tid*EDG + 0] = 0.f;  s_eL[(CH+tid)*EDG + 0] = 0.f;   // k(0) sentinels
        s_kt[tid*8 + 6] = 0.f;    s_kt[tid*8 + 7] = 0.f;          // k(1031+) sentinels
        s_kt[(CH+tid)*8 + 6] = 0.f; s_kt[(CH+tid)*8 + 7] = 0.f;
    }
    #pragma unroll
    for (int ch=0; ch<CH; ch++){
        const float* sc = src + ((size_t)b*CH + ch)*NPT;
        for (int p=tid; p<EXT; p+=RKTHREADS){
            int g = gofs + p;
            s_su[ch*EXT + p] = ((unsigned)g < NPT) ? sc[g] : 0.f;
        }
    }
    __syncthreads();

    float cu[CH][2], kr[CH][2], acc[CH][2], acct[CH];
    #pragma unroll
    for (int co=0; co<CH; co++){
        acct[co]=0.f; acc[co][0]=0.f; acc[co][1]=0.f;
    }

    float* eL0 = s_eL;            float* eL1 = s_eL + CH*EDG;
    float* eR0 = s_eR;            float* eR1 = s_eR + CH*EDG;
    float* kt0 = s_kt;            float* kt1 = s_kt + CH*8;

    stage<0>(cu, eL0,eR0,kt0, eL0,eR0,kt0, s_su, 0.f,     1.f, gofs, tid, edge, kr, acc, acct);
    stage<1>(cu, eL0,eR0,kt0, eL1,eR1,kt1, s_su, 0.5f*dt, 2.f, gofs, tid, edge, kr, acc, acct);
    stage<2>(cu, eL1,eR1,kt1, eL0,eR0,kt0, s_su, 0.5f*dt, 2.f, gofs, tid, edge, kr, acc, acct);
    stage<3>(cu, eL0,eR0,kt0, eL1,eR1,kt1, s_su, dt,      1.f, gofs, tid, edge, kr, acc, acct);

    const float dt6 = dt * (1.0f/6.0f);
    const int p0 = 2*tid;
    #pragma unroll
    for (int co=0; co<CH; co++){
        float* dp = dst + ((size_t)b*CH + co)*NPT + gofs;
        const float* ru = s_su + co*EXT + p0;
        float u1 = ru[1];
        float u2 = ru[2];
        int p1 = p0 + 1, p2 = p0 + 2;
        if (p1 >= HALO) dp[p1] = u1 + dt6 * acc[co][0];
        if (p2 >= HALO) dp[p2] = u2 + dt6 * acc[co][1];
    }
    if (tid < 3){
        int p = TILE + 1 + tid;      // 1025..1027, central
        #pragma unroll
        for (int co=0; co<CH; co++)
            dst[((size_t)b*CH + co)*NPT + gofs + p] = s_su[co*EXT + p] + dt6 * acct[co];
    }
}

// ---------------- forward 16-mode DFT (partial sums) ----------------
__global__ void __launch_bounds__(256)
fwd_dft_kernel(const float* __restrict__ u)
{
    const int blk  = blockIdx.x;                 // [0, BB*CH*FBLK)
    const int seg  = blk & (FBLK-1);
    const int bi   = blk / FBLK;                 // b*CH + i
    const int tid  = threadIdx.x;
    const int lane = tid & 31, warp = tid >> 5;
    const int n0   = seg*8192 + warp*1024 + lane;  // stride-32 walk, coalesced
    const float* x = u + (size_t)bi*NPT;

    const float TWO_PI = 6.283185307179586f;
    float cr[MODES], cim[MODES], ck[MODES], sk[MODES], dc[MODES], ds[MODES];
    #pragma unroll
    for (int k=0; k<MODES; k++){
        cr[k]=0.f; cim[k]=0.f;
        float a0 = TWO_PI * ((float)((k*n0) & NMASK) * (1.0f/NPT));
        sincosf(a0, &sk[k], &ck[k]);
        float ad = TWO_PI * ((float)(k*32) * (1.0f/NPT));
        sincosf(ad, &ds[k], &dc[k]);
    }
    #pragma unroll 2
    for (int j=0; j<32; j++){
        float v = __ldg(&x[n0 + (j<<5)]);
        #pragma unroll
        for (int k=0; k<MODES; k++){
            cr[k]  = fmaf( v, ck[k], cr[k]);     // X += u * e^{-i theta}
            cim[k] = fmaf(-v, sk[k], cim[k]);
            float nc = ck[k]*dc[k] - sk[k]*ds[k];
            sk[k] = fmaf(ck[k], ds[k], sk[k]*dc[k]);
            ck[k] = nc;
        }
    }
    #pragma unroll
    for (int k=0; k<MODES; k++){
        #pragma unroll
        for (int off=16; off; off>>=1){
            cr[k]  += __shfl_xor_sync(0xffffffffu, cr[k],  off);
            cim[k] += __shfl_xor_sync(0xffffffffu, cim[k], off);
        }
    }
    __shared__ float red[8][MODES*2];
    if (lane == 0){
        #pragma unroll
        for (int k=0; k<MODES; k++){
            red[warp][2*k]   = cr[k];
            red[warp][2*k+1] = cim[k];
        }
    }
    __syncthreads();
    if (tid < MODES*2){
        float s = 0.f;
        #pragma unroll
        for (int w=0; w<8; w++) s += red[w][tid];
        g_part[(bi*FBLK + seg)*(MODES*2) + tid] = s;
    }
}

// ---------------- mix: reduce partials, fold proj into mode weights ----------------
__global__ void mix_kernel(const float* __restrict__ sw_r, const float* __restrict__ sw_i,
                           const float* __restrict__ proj_w)
{
    const int b = blockIdx.x;
    const int t = threadIdx.x;         // 96 = CH*MODES
    const int o = t / MODES, k = t % MODES;
    float Zr = 0.f, Zi = 0.f;
    #pragma unroll
    for (int i=0; i<CH; i++){
        float Xr=0.f, Xi=0.f;
        int bi = b*CH + i;
        #pragma unroll
        for (int s=0; s<FBLK; s++){
            Xr += g_part[(bi*FBLK+s)*(MODES*2) + 2*k];
            Xi += g_part[(bi*FBLK+s)*(MODES*2) + 2*k + 1];
        }
        float Wr=0.f, Wi=0.f;
        #pragma unroll
        for (int c=0; c<CH; c++){
            float pw = proj_w[o*CH + c];
            Wr = fmaf(sw_r[(i*CH+c)*MODES + k], pw, Wr);
            Wi = fmaf(sw_i[(i*CH+c)*MODES + k], pw, Wi);
        }
        Zr += Xr*Wr - Xi*Wi;
        Zi += Xr*Wi + Xi*Wr;
    }
    float scale = (k==0) ? (1.0f/NPT) : (2.0f/NPT);   // irfft: DC once, others doubled
    g_Z[(b*CH+o)*MODES*2 + 2*k]     = Zr*scale;
    g_Z[(b*CH+o)*MODES*2 + 2*k + 1] = Zi*scale;
}

// ---------------- synthesis: 16-mode irfft + bias ----------------
__global__ void __launch_bounds__(256)
synth_kernel(float* __restrict__ out, const float* __restrict__ proj_b)
{
    const int blk  = blockIdx.x;        // b*8 + seg
    const int b    = blk >> 3, seg = blk & 7;
    const int tid  = threadIdx.x, lane = tid & 31, warp = tid >> 5;
    const int n0   = seg*8192 + warp*1024 + lane;

    __shared__ float zz[CH*MODES*2];
    __shared__ float pb[CH];
    if (tid < CH*MODES*2) zz[tid] = g_Z[b*CH*MODES*2 + tid];
    if (tid < CH)         pb[tid] = proj_b[tid];
    __syncthreads();

    const float TWO_PI = 6.283185307179586f;
    float ck[MODES], sk[MODES], dc[MODES], ds[MODES];
    #pragma unroll
    for (int k=0; k<MODES; k++){
        float a0 = TWO_PI * ((float)((k*n0) & NMASK) * (1.0f/NPT));
        sincosf(a0, &sk[k], &ck[k]);
        float ad = TWO_PI * ((float)(k*32) * (1.0f/NPT));
        sincosf(ad, &ds[k], &dc[k]);
    }
    for (int j=0; j<32; j++){
        int n = n0 + (j<<5);
        float accv[CH];
        #pragma unroll
        for (int o=0; o<CH; o++) accv[o] = pb[o];
        #pragma unroll
        for (int k=0; k<MODES; k++){
            float c = ck[k], s = sk[k];
            #pragma unroll
            for (int o=0; o<CH; o++){
                accv[o] = fmaf( zz[(o*MODES+k)*2],     c, accv[o]);
                accv[o] = fmaf(-zz[(o*MODES+k)*2 + 1], s, accv[o]);
            }
            float nc = c*dc[k] - s*ds[k];
            sk[k] = fmaf(c, ds[k], s*dc[k]);
            ck[k] = nc;
        }
        #pragma unroll
        for (int o=0; o<CH; o++)
            out[((size_t)(b*CH + o))*NPT + n] = accv[o];
    }
}

// ---------------- launch ----------------
extern "C" void kernel_launch(void* const* d_in, const int* in_sizes, int n_in,
                              void* d_out, int out_size)
{
    const float* u0     = (const float*)d_in[0];
    const float* t_span = (const float*)d_in[1];
    const float* conv_w = (const float*)d_in[2];
    const float* conv_b = (const float*)d_in[3];
    const float* sw_r   = (const float*)d_in[4];
    const float* sw_i   = (const float*)d_in[5];
    const float* proj_w = (const float*)d_in[6];
    const float* proj_b = (const float*)d_in[7];
    float* out = (float*)d_out;

    float *bufA = nullptr, *bufB = nullptr;
    cudaGetSymbolAddress((void**)&bufA, g_bufA);
    cudaGetSymbolAddress((void**)&bufB, g_bufB);

    cudaMemcpyToSymbolAsync(c_w, conv_w, CH*CH*3*sizeof(float), 0,
                            cudaMemcpyDeviceToDevice, 0);
    cudaMemcpyToSymbolAsync(c_b, conv_b, CH*sizeof(float), 0,
                            cudaMemcpyDeviceToDevice, 0);

    const int rk_smem = (CH*EXT + 4*CH*EDG + 4*CH*8) * sizeof(float);
    cudaFuncSetAttribute(rk4_kernel, cudaFuncAttributeMaxDynamicSharedMemorySize, rk_smem);

    dim3 rkgrid(NPT/TILE, BB);
    const float* src = u0;
    for (int s=0; s<TSTEPS-1; s++){
        float* dstb = (s & 1) ? bufB : bufA;
        rk4_kernel<<<rkgrid, RKTHREADS, rk_smem>>>(src, dstb, t_span, s);
        src = dstb;
    }
    fwd_dft_kernel<<<BB*CH*FBLK, 256>>>(src);
    mix_kernel<<<BB, CH*MODES>>>(sw_r, sw_i, proj_w);
    synth_kernel<<<BB*8, 256>>>(out, proj_b);
}

// round 6
// speedup vs baseline: 1.4077x; 1.4077x over previous
#include <cuda_runtime.h>

#define CH 6
#define MODES 16
#define BB 32
#define NPT 65536
#define NMASK 65535
#define TSTEPS 8

#define HALO7 28                 // 7 steps x halo 4
#define EXT 1032                 // smem window per block
#define CORE 976                 // EXT - 2*HALO7 valid output core [28,1004)
#define NBLK 68                  // ceil(NPT/CORE)
#define RKTHREADS 256            // 4 points per thread
#define EDG 260                  // per-channel stride in edge arrays
#define FBLK 8                   // blocks per (b,i) in forward DFT

typedef unsigned long long ull;

// -------- scratch (no allocations allowed) --------
__device__ float  g_bufA[BB*CH*NPT];
__device__ float  g_part[BB*CH*FBLK*MODES*2];
__device__ float  g_Z[BB*CH*MODES*2];
__device__ float2 g_pack[CH*CH*3 + CH];    // staging for packed constants

__constant__ float  c_w[CH*CH*3];          // scalar weights (tail path)
__constant__ float  c_b[CH];
__constant__ float2 c_w2[CH*CH*3];         // duplicated pairs (w,w)
__constant__ float2 c_b2[CH];

__device__ __forceinline__ float htanh(float x){
    float y;
    asm("tanh.approx.f32 %0, %1;" : "=f"(y) : "f"(x));
    return y;
}
__device__ __forceinline__ ull pk2(float lo, float hi){
    ull r; asm("mov.b64 %0, {%1, %2};" : "=l"(r) : "f"(lo), "f"(hi)); return r;
}
__device__ __forceinline__ void upk2(ull v, float& lo, float& hi){
    asm("mov.b64 {%0, %1}, %2;" : "=f"(lo), "=f"(hi) : "l"(v));
}
__device__ __forceinline__ ull fma2(ull a, ull b, ull c){
    ull d; asm("fma.rn.f32x2 %0, %1, %2, %3;" : "=l"(d) : "l"(a), "l"(b), "l"(c)); return d;
}
__device__ __forceinline__ ull add2(ull a, ull b){
    ull d; asm("add.rn.f32x2 %0, %1, %2;" : "=l"(d) : "l"(a), "l"(b)); return d;
}

__global__ void init_pack_kernel(const float* __restrict__ conv_w,
                                 const float* __restrict__ conv_b){
    int i = threadIdx.x;
    if (i < CH*CH*3) g_pack[i] = make_float2(conv_w[i], conv_w[i]);
    if (i < CH)      g_pack[CH*CH*3 + i] = make_float2(conv_b[i], conv_b[i]);
}

// ---------------- fused 7-step RK4 kernel ----------------
// Per step: identical machinery to the per-step kernel (4 pts/thread,
// reg-resident k, linearity split cu=conv(u), double-buffered edge arrays,
// tail positions [1025,1031) by tid<6), but u lives in smem across steps.
// Validity: step s update correct on [4s+4, 1028-4s); final core [28,1004).
// Conv math packed with fma.rn.f32x2 over point-pairs (j0,j1),(j2,j3).

template<int S>
__device__ __forceinline__ void stage_p(
    ull (&cu2)[CH][2],
    const float* __restrict__ eLr, const float* __restrict__ eRr,
    const float* __restrict__ ktr,
    float* __restrict__ eLw, float* __restrict__ eRw, float* __restrict__ ktw,
    const float* __restrict__ su,
    float cc, ull cc2, ull aw2, float aw,
    int gofs, int tid, bool edge,
    float (&kr)[CH][4], ull (&acc2)[CH][2], float (&acct)[CH])
{
    const int p0 = 4*tid;
    const ull* cw2 = (const ull*)c_w2;
    const ull* cb2 = (const ull*)c_b2;

    ull a2[CH][2];
    #pragma unroll
    for (int co=0; co<CH; co++){ a2[co][0]=0ull; a2[co][1]=0ull; }

    #pragma unroll
    for (int ci=0; ci<CH; ci++){
        ull x01, x12, x23, x34, x45;
        if (S == 0){
            const float* ru = su + ci*EXT + p0;
            float2 A = *(const float2*)ru;        // xv0,xv1
            float2 Bv = *(const float2*)(ru + 2); // xv2,xv3
            float2 Cv = *(const float2*)(ru + 4); // xv4,xv5
            x01 = pk2(A.x,  A.y);
            x12 = pk2(A.y,  Bv.x);
            x23 = pk2(Bv.x, Bv.y);
            x34 = pk2(Bv.y, Cv.x);
            x45 = pk2(Cv.x, Cv.y);
        } else {
            float k0 = eLr[ci*EDG + tid];
            float k1 = kr[ci][0], k2 = kr[ci][1], k3 = kr[ci][2], k4 = kr[ci][3];
            float k5 = eRr[ci*EDG + tid + 1];
            if (edge){
                if ((unsigned)(gofs + p0 + 0) >= NPT) k0 = 0.f;
                if ((unsigned)(gofs + p0 + 1) >= NPT) k1 = 0.f;
                if ((unsigned)(gofs + p0 + 2) >= NPT) k2 = 0.f;
                if ((unsigned)(gofs + p0 + 3) >= NPT) k3 = 0.f;
                if ((unsigned)(gofs + p0 + 4) >= NPT) k4 = 0.f;
                if ((unsigned)(gofs + p0 + 5) >= NPT) k5 = 0.f;
            }
            x01 = pk2(k0, k1);
            x12 = pk2(k1, k2);
            x23 = pk2(k2, k3);
            x34 = pk2(k3, k4);
            x45 = pk2(k4, k5);
        }
        #pragma unroll
        for (int co=0; co<CH; co++){
            const ull w0d = cw2[(co*CH+ci)*3 + 0];
            const ull w1d = cw2[(co*CH+ci)*3 + 1];
            const ull w2d = cw2[(co*CH+ci)*3 + 2];
            a2[co][0] = fma2(w0d, x01, fma2(w1d, x12, fma2(w2d, x23, a2[co][0])));
            a2[co][1] = fma2(w0d, x23, fma2(w1d, x34, fma2(w2d, x45, a2[co][1])));
        }
    }

    if (S == 0){
        #pragma unroll
        for (int co=0; co<CH; co++){ cu2[co][0]=a2[co][0]; cu2[co][1]=a2[co][1]; }
    } else {
        #pragma unroll
        for (int co=0; co<CH; co++){
            a2[co][0] = fma2(cc2, a2[co][0], cu2[co][0]);
            a2[co][1] = fma2(cc2, a2[co][1], cu2[co][1]);
        }
    }

    // tail point p = 1025+tid for tid<6 (scalar path via smem)
    float ttail[CH];
    if (tid < 6){
        const int p = 1025 + tid;
        #pragma unroll
        for (int co=0; co<CH; co++) ttail[co] = 0.f;
        #pragma unroll
        for (int ci=0; ci<CH; ci++){
            float vv[3];
            #pragma unroll
            for (int t3=0; t3<3; t3++){
                int pp = p - 1 + t3;                 // 1024..1031
                float v = su[ci*EXT + pp];
                if (S > 0){
                    float kv = (pp == 1024) ? eLr[ci*EDG + RKTHREADS]
                                            : ktr[ci*8 + (pp - 1025)];
                    v = fmaf(cc, kv, v);
                }
                if ((unsigned)(gofs + pp) >= NPT) v = 0.f;
                vv[t3] = v;
            }
            #pragma unroll
            for (int co=0; co<CH; co++){
                const float w0 = c_w[(co*CH+ci)*3 + 0];
                const float w1 = c_w[(co*CH+ci)*3 + 1];
                const float w2 = c_w[(co*CH+ci)*3 + 2];
                ttail[co] = fmaf(w0, vv[0], fmaf(w1, vv[1], fmaf(w2, vv[2], ttail[co])));
            }
        }
    }

    #pragma unroll
    for (int co=0; co<CH; co++){
        ull ab0 = add2(a2[co][0], cb2[co]);
        ull ab1 = add2(a2[co][1], cb2[co]);
        float t0,t1,t2,t3;
        upk2(ab0, t0, t1);  upk2(ab1, t2, t3);
        t0 = htanh(t0); t1 = htanh(t1); t2 = htanh(t2); t3 = htanh(t3);
        acc2[co][0] = fma2(aw2, pk2(t0,t1), acc2[co][0]);
        acc2[co][1] = fma2(aw2, pk2(t2,t3), acc2[co][1]);
        kr[co][0]=t0; kr[co][1]=t1; kr[co][2]=t2; kr[co][3]=t3;
        if (S < 3){
            eLw[co*EDG + tid + 1] = t3;   // k(4t+4)
            eRw[co*EDG + tid]     = t0;   // k(4t+1)
        }
    }
    if (tid < 6){
        #pragma unroll
        for (int co=0; co<CH; co++){
            float t = htanh(ttail[co] + c_b[co]);
            if (S < 3){
                ktw[co*8 + tid] = t;
                if (tid == 0) eRw[co*EDG + RKTHREADS] = t;   // k(1025)
            }
            if (tid < 3) acct[co] = fmaf(aw, t, acct[co]);
        }
    }
    if (S < 3) __syncthreads();
}

__global__ void __launch_bounds__(RKTHREADS, 2)
rk4_fused(const float* __restrict__ src, float* __restrict__ dst,
          const float* __restrict__ t_span)
{
    extern __shared__ float sm[];
    float* s_su = sm;                      // CH*EXT
    float* s_eL = s_su + CH*EXT;           // 2*CH*EDG
    float* s_eR = s_eL + 2*CH*EDG;         // 2*CH*EDG
    float* s_kt = s_eR + 2*CH*EDG;         // 2*CH*8

    const int b    = blockIdx.y;
    const int bx   = blockIdx.x;
    const int gofs = bx*CORE - HALO7;
    const int tid  = threadIdx.x;
    const bool edge = (bx == 0) | (bx == gridDim.x - 1);

    if (tid < CH){
        s_eL[tid*EDG + 0] = 0.f;  s_eL[(CH+tid)*EDG + 0] = 0.f;   // k(0) sentinels
        s_kt[tid*8 + 6] = 0.f;    s_kt[tid*8 + 7] = 0.f;          // k(1031+) sentinels
        s_kt[(CH+tid)*8 + 6] = 0.f; s_kt[(CH+tid)*8 + 7] = 0.f;
    }
    #pragma unroll
    for (int ch=0; ch<CH; ch++){
        const float* sc = src + ((size_t)b*CH + ch)*NPT;
        for (int p=tid; p<EXT; p+=RKTHREADS){
            int g = gofs + p;
            s_su[ch*EXT + p] = ((unsigned)g < NPT) ? sc[g] : 0.f;
        }
    }
    __syncthreads();

    float* eL0 = s_eL;  float* eL1 = s_eL + CH*EDG;
    float* eR0 = s_eR;  float* eR1 = s_eR + CH*EDG;
    float* kt0 = s_kt;  float* kt1 = s_kt + CH*8;

    const ull one2 = pk2(1.f, 1.f);
    const ull two2 = pk2(2.f, 2.f);
    const int p0 = 4*tid;

    #pragma unroll 1
    for (int s=0; s<TSTEPS-1; s++){
        const float dt  = t_span[s+1] - t_span[s];
        const float hdt = 0.5f*dt;
        const ull hdt2 = pk2(hdt, hdt);
        const ull dt2  = pk2(dt, dt);

        ull cu2[CH][2], acc2[CH][2];
        float kr[CH][4], acct[CH];
        #pragma unroll
        for (int co=0; co<CH; co++){
            acct[co]=0.f; acc2[co][0]=0ull; acc2[co][1]=0ull;
        }

        stage_p<0>(cu2, eL0,eR0,kt0, eL0,eR0,kt0, s_su, 0.f, 0ull, one2, 1.f,
                   gofs, tid, edge, kr, acc2, acct);
        stage_p<1>(cu2, eL0,eR0,kt0, eL1,eR1,kt1, s_su, hdt, hdt2, two2, 2.f,
                   gofs, tid, edge, kr, acc2, acct);
        stage_p<2>(cu2, eL1,eR1,kt1, eL0,eR0,kt0, s_su, hdt, hdt2, two2, 2.f,
                   gofs, tid, edge, kr, acc2, acct);
        stage_p<3>(cu2, eL0,eR0,kt0, eL1,eR1,kt1, s_su, dt,  dt2,  one2, 1.f,
                   gofs, tid, edge, kr, acc2, acct);

        __syncthreads();            // stage-3 reads of su/edges complete

        const float dt6 = dt * (1.0f/6.0f);
        #pragma unroll
        for (int co=0; co<CH; co++){
            float a0,a1,a2v,a3;
            upk2(acc2[co][0], a0, a1);
            upk2(acc2[co][1], a2v, a3);
            float av[4] = {a0, a1, a2v, a3};
            float* rp = s_su + co*EXT + p0;
            #pragma unroll
            for (int j=0; j<4; j++){
                int g = gofs + p0 + 1 + j;
                if (!edge || (unsigned)g < NPT)
                    rp[1+j] += dt6 * av[j];
            }
        }
        if (tid < 3){
            int p = 1025 + tid;
            int g = gofs + p;
            if (!edge || (unsigned)g < NPT){
                #pragma unroll
                for (int co=0; co<CH; co++)
                    s_su[co*EXT + p] += dt6 * acct[co];
            }
        }
        __syncthreads();            // updated su visible to next step
    }

    // final store: core [28, 1004)
    #pragma unroll
    for (int co=0; co<CH; co++){
        float* dp = dst + ((size_t)b*CH + co)*NPT;
        const float* rp = s_su + co*EXT + p0;
        #pragma unroll
        for (int j=0; j<4; j++){
            int p = p0 + 1 + j;
            int g = gofs + p;
            if (p >= HALO7 && p < EXT-HALO7 && (unsigned)g < NPT)
                dp[g] = rp[1+j];
        }
    }
}

// ---------------- forward 16-mode DFT (partial sums) ----------------
__global__ void __launch_bounds__(256)
fwd_dft_kernel(const float* __restrict__ u)
{
    const int blk  = blockIdx.x;                 // [0, BB*CH*FBLK)
    const int seg  = blk & (FBLK-1);
    const int bi   = blk / FBLK;                 // b*CH + i
    const int tid  = threadIdx.x;
    const int lane = tid & 31, warp = tid >> 5;
    const int n0   = seg*8192 + warp*1024 + lane;  // stride-32 walk, coalesced
    const float* x = u + (size_t)bi*NPT;

    const float TWO_PI = 6.283185307179586f;
    float cr[MODES], cim[MODES], ck[MODES], sk[MODES], dc[MODES], ds[MODES];
    #pragma unroll
    for (int k=0; k<MODES; k++){
        cr[k]=0.f; cim[k]=0.f;
        float a0 = TWO_PI * ((float)((k*n0) & NMASK) * (1.0f/NPT));
        sincosf(a0, &sk[k], &ck[k]);
        float ad = TWO_PI * ((float)(k*32) * (1.0f/NPT));
        sincosf(ad, &ds[k], &dc[k]);
    }
    #pragma unroll 2
    for (int j=0; j<32; j++){
        float v = __ldg(&x[n0 + (j<<5)]);
        #pragma unroll
        for (int k=0; k<MODES; k++){
            cr[k]  = fmaf( v, ck[k], cr[k]);     // X += u * e^{-i theta}
            cim[k] = fmaf(-v, sk[k], cim[k]);
            float nc = ck[k]*dc[k] - sk[k]*ds[k];
            sk[k] = fmaf(ck[k], ds[k], sk[k]*dc[k]);
            ck[k] = nc;
        }
    }
    #pragma unroll
    for (int k=0; k<MODES; k++){
        #pragma unroll
        for (int off=16; off; off>>=1){
            cr[k]  += __shfl_xor_sync(0xffffffffu, cr[k],  off);
            cim[k] += __shfl_xor_sync(0xffffffffu, cim[k], off);
        }
    }
    __shared__ float red[8][MODES*2];
    if (lane == 0){
        #pragma unroll
        for (int k=0; k<MODES; k++){
            red[warp][2*k]   = cr[k];
            red[warp][2*k+1] = cim[k];
        }
    }
    __syncthreads();
    if (tid < MODES*2){
        float s = 0.f;
        #pragma unroll
        for (int w=0; w<8; w++) s += red[w][tid];
        g_part[(bi*FBLK + seg)*(MODES*2) + tid] = s;
    }
}

// ---------------- mix: reduce partials, fold proj into mode weights ----------------
__global__ void mix_kernel(const float* __restrict__ sw_r, const float* __restrict__ sw_i,
                           const float* __restrict__ proj_w)
{
    const int b = blockIdx.x;
    const int t = threadIdx.x;         // 96 = CH*MODES
    const int o = t / MODES, k = t % MODES;
    float Zr = 0.f, Zi = 0.f;
    #pragma unroll
    for (int i=0; i<CH; i++){
        float Xr=0.f, Xi=0.f;
        int bi = b*CH + i;
        #pragma unroll
        for (int s=0; s<FBLK; s++){
            Xr += g_part[(bi*FBLK+s)*(MODES*2) + 2*k];
            Xi += g_part[(bi*FBLK+s)*(MODES*2) + 2*k + 1];
        }
        float Wr=0.f, Wi=0.f;
        #pragma unroll
        for (int c=0; c<CH; c++){
            float pw = proj_w[o*CH + c];
            Wr = fmaf(sw_r[(i*CH+c)*MODES + k], pw, Wr);
            Wi = fmaf(sw_i[(i*CH+c)*MODES + k], pw, Wi);
        }
        Zr += Xr*Wr - Xi*Wi;
        Zi += Xr*Wi + Xi*Wr;
    }
    float scale = (k==0) ? (1.0f/NPT) : (2.0f/NPT);   // irfft: DC once, others doubled
    g_Z[(b*CH+o)*MODES*2 + 2*k]     = Zr*scale;
    g_Z[(b*CH+o)*MODES*2 + 2*k + 1] = Zi*scale;
}

// ---------------- synthesis: 16-mode irfft + bias ----------------
__global__ void __launch_bounds__(256)
synth_kernel(float* __restrict__ out, const float* __restrict__ proj_b)
{
    const int blk  = blockIdx.x;        // b*8 + seg
    const int b    = blk >> 3, seg = blk & 7;
    const int tid  = threadIdx.x, lane = tid & 31, warp = tid >> 5;
    const int n0   = seg*8192 + warp*1024 + lane;

    __shared__ float zz[CH*MODES*2];
    __shared__ float pb[CH];
    if (tid < CH*MODES*2) zz[tid] = g_Z[b*CH*MODES*2 + tid];
    if (tid < CH)         pb[tid] = proj_b[tid];
    __syncthreads();

    const float TWO_PI = 6.283185307179586f;
    float ck[MODES], sk[MODES], dc[MODES], ds[MODES];
    #pragma unroll
    for (int k=0; k<MODES; k++){
        float a0 = TWO_PI * ((float)((k*n0) & NMASK) * (1.0f/NPT));
        sincosf(a0, &sk[k], &ck[k]);
        float ad = TWO_PI * ((float)(k*32) * (1.0f/NPT));
        sincosf(ad, &ds[k], &dc[k]);
    }
    for (int j=0; j<32; j++){
        int n = n0 + (j<<5);
        float accv[CH];
        #pragma unroll
        for (int o=0; o<CH; o++) accv[o] = pb[o];
        #pragma unroll
        for (int k=0; k<MODES; k++){
            float c = ck[k], s = sk[k];
            #pragma unroll
            for (int o=0; o<CH; o++){
                accv[o] = fmaf( zz[(o*MODES+k)*2],     c, accv[o]);
                accv[o] = fmaf(-zz[(o*MODES+k)*2 + 1], s, accv[o]);
            }
            float nc = c*dc[k] - s*ds[k];
            sk[k] = fmaf(c, ds[k], s*dc[k]);
            ck[k] = nc;
        }
        #pragma unroll
        for (int o=0; o<CH; o++)
            out[((size_t)(b*CH + o))*NPT + n] = accv[o];
    }
}

// ---------------- launch ----------------
extern "C" void kernel_launch(void* const* d_in, const int* in_sizes, int n_in,
                              void* d_out, int out_size)
{
    const float* u0     = (const float*)d_in[0];
    const float* t_span = (const float*)d_in[1];
    const float* conv_w = (const float*)d_in[2];
    const float* conv_b = (const float*)d_in[3];
    const float* sw_r   = (const float*)d_in[4];
    const float* sw_i   = (const float*)d_in[5];
    const float* proj_w = (const float*)d_in[6];
    const float* proj_b = (const float*)d_in[7];
    float* out = (float*)d_out;

    float*  bufA = nullptr;
    float2* packp = nullptr;
    cudaGetSymbolAddress((void**)&bufA, g_bufA);
    cudaGetSymbolAddress((void**)&packp, g_pack);

    cudaMemcpyToSymbolAsync(c_w, conv_w, CH*CH*3*sizeof(float), 0,
                            cudaMemcpyDeviceToDevice, 0);
    cudaMemcpyToSymbolAsync(c_b, conv_b, CH*sizeof(float), 0,
                            cudaMemcpyDeviceToDevice, 0);
    init_pack_kernel<<<1, 128>>>(conv_w, conv_b);
    cudaMemcpyToSymbolAsync(c_w2, packp, CH*CH*3*sizeof(float2), 0,
                            cudaMemcpyDeviceToDevice, 0);
    cudaMemcpyToSymbolAsync(c_b2, packp + CH*CH*3, CH*sizeof(float2), 0,
                            cudaMemcpyDeviceToDevice, 0);

    const int rk_smem = (CH*EXT + 4*CH*EDG + 4*CH*8) * sizeof(float);
    cudaFuncSetAttribute(rk4_fused, cudaFuncAttributeMaxDynamicSharedMemorySize, rk_smem);

    dim3 rkgrid(NBLK, BB);
    rk4_fused<<<rkgrid, RKTHREADS, rk_smem>>>(u0, bufA, t_span);

    fwd_dft_kernel<<<BB*CH*FBLK, 256>>>(bufA);
    mix_kernel<<<BB, CH*MODES>>>(sw_r, sw_i, proj_w);
    synth_kernel<<<BB*8, 256>>>(out, proj_b);
}

// round 7
// speedup vs baseline: 2.7635x; 1.9632x over previous
#include <cuda_runtime.h>

#define CH 6
#define MODES 16
#define BB 32
#define NPT 65536
#define NMASK 65535
#define TSTEPS 8

#define HALO7 28                 // 7 steps x halo 4
#define EXT 1032                 // smem window per block
#define CORE 976                 // EXT - 2*HALO7, valid output core [28,1004)
#define NBLK 68                  // ceil(NPT/CORE)
#define RKTHREADS 256            // 4 points per thread
#define EDG 260                  // per-channel stride in edge arrays
#define FBLK 8                   // blocks per (b,i) in forward DFT

// -------- scratch (no allocations allowed) --------
__device__ float g_bufA[BB*CH*NPT];
__device__ float g_part[BB*CH*FBLK*MODES*2];
__device__ float g_Z[BB*CH*MODES*2];

__constant__ float c_w[CH*CH*3];   // [co][ci][3]
__constant__ float c_b[CH];

__device__ __forceinline__ float htanh(float x){
    float y;
    asm("tanh.approx.f32 %0, %1;" : "=f"(y) : "f"(x));
    return y;
}

// ---------------- stage (identical machinery to best per-step kernel) ----------------
// 4 points/thread: own p0+1..p0+4, window [p0, p0+5].
// Linearity split: conv(u + c*k) = conv(u) + c*conv(k); cu = conv(u) in regs.
// Edge arrays (double-buffered, stride-1, conflict-free), 1 barrier/stage:
//   eL[i] = k(4i)   (i=0 sentinel; thread t writes i=t+1 <- kr[3])
//   eR[i] = k(4i+1) (thread t writes i=t <- kr[0]; i=256 <- tail k(1025))
// Tail positions [1025,1031) handled by tid<6 via kt (full u+ck path on smem).

template<int S>
__device__ __forceinline__ void stage(
    float (&cu)[CH][4],
    const float* __restrict__ eLr, const float* __restrict__ eRr,
    const float* __restrict__ ktr,
    float* __restrict__ eLw, float* __restrict__ eRw, float* __restrict__ ktw,
    const float* __restrict__ su,
    float cc, float aw, int gofs, int tid, bool edge,
    float (&kr)[CH][4], float (&acc)[CH][4], float (&acct)[CH])
{
    const int p0 = 4*tid;
    float a[CH][4];
    #pragma unroll
    for (int co=0; co<CH; co++){ a[co][0]=0.f; a[co][1]=0.f; a[co][2]=0.f; a[co][3]=0.f; }

    if (S == 0){
        // a = conv(u); u window from smem (masked at load / kept masked by update guard)
        #pragma unroll
        for (int ci=0; ci<CH; ci++){
            const float* ru = su + ci*EXT + p0;
            float4 u0 = *(const float4*)ru;
            float2 u1 = *(const float2*)(ru + 4);
            float xv[6] = {u0.x, u0.y, u0.z, u0.w, u1.x, u1.y};
            #pragma unroll
            for (int co=0; co<CH; co++){
                const float w0 = c_w[(co*CH+ci)*3 + 0];
                const float w1 = c_w[(co*CH+ci)*3 + 1];
                const float w2 = c_w[(co*CH+ci)*3 + 2];
                #pragma unroll
                for (int j=0; j<4; j++)
                    a[co][j] = fmaf(w0, xv[j], fmaf(w1, xv[j+1], fmaf(w2, xv[j+2], a[co][j])));
            }
        }
        #pragma unroll
        for (int co=0; co<CH; co++)
            #pragma unroll
            for (int j=0; j<4; j++) cu[co][j] = a[co][j];
    } else {
        // a = cu + cc * conv(k)
        #pragma unroll
        for (int ci=0; ci<CH; ci++){
            float xvk[6];
            xvk[0] = eLr[ci*EDG + tid];
            xvk[1] = kr[ci][0]; xvk[2] = kr[ci][1];
            xvk[3] = kr[ci][2]; xvk[4] = kr[ci][3];
            xvk[5] = eRr[ci*EDG + tid + 1];
            if (edge){
                #pragma unroll
                for (int j=0; j<6; j++)
                    if ((unsigned)(gofs + p0 + j) >= NPT) xvk[j] = 0.f;
            }
            #pragma unroll
            for (int co=0; co<CH; co++){
                const float w0 = c_w[(co*CH+ci)*3 + 0];
                const float w1 = c_w[(co*CH+ci)*3 + 1];
                const float w2 = c_w[(co*CH+ci)*3 + 2];
                #pragma unroll
                for (int j=0; j<4; j++)
                    a[co][j] = fmaf(w0, xvk[j], fmaf(w1, xvk[j+1], fmaf(w2, xvk[j+2], a[co][j])));
            }
        }
        #pragma unroll
        for (int co=0; co<CH; co++)
            #pragma unroll
            for (int j=0; j<4; j++) a[co][j] = fmaf(cc, a[co][j], cu[co][j]);
    }

    // tail point p = 1025+tid for tid<6 (full u + cc*k path via smem)
    float ttail[CH];
    if (tid < 6){
        const int p = 1025 + tid;
        #pragma unroll
        for (int co=0; co<CH; co++) ttail[co] = 0.f;
        #pragma unroll
        for (int ci=0; ci<CH; ci++){
            float vv[3];
            #pragma unroll
            for (int t3=0; t3<3; t3++){
                int pp = p - 1 + t3;                 // 1024..1031
                float v = su[ci*EXT + pp];
                if (S > 0){
                    float kv = (pp == 1024) ? eLr[ci*EDG + RKTHREADS]
                                            : ktr[ci*8 + (pp - 1025)];
                    v = fmaf(cc, kv, v);
                }
                if ((unsigned)(gofs + pp) >= NPT) v = 0.f;
                vv[t3] = v;
            }
            #pragma unroll
            for (int co=0; co<CH; co++){
                const float w0 = c_w[(co*CH+ci)*3 + 0];
                const float w1 = c_w[(co*CH+ci)*3 + 1];
                const float w2 = c_w[(co*CH+ci)*3 + 2];
                ttail[co] = fmaf(w0, vv[0], fmaf(w1, vv[1], fmaf(w2, vv[2], ttail[co])));
            }
        }
    }

    #pragma unroll
    for (int co=0; co<CH; co++){
        const float bias = c_b[co];
        #pragma unroll
        for (int j=0; j<4; j++){
            float t = htanh(a[co][j] + bias);
            kr[co][j] = t;
            acc[co][j] = fmaf(aw, t, acc[co][j]);
        }
        if (S < 3){
            eLw[co*EDG + tid + 1] = kr[co][3];
            eRw[co*EDG + tid]     = kr[co][0];
        }
    }
    if (tid < 6){
        #pragma unroll
        for (int co=0; co<CH; co++){
            float t = htanh(ttail[co] + c_b[co]);
            if (S < 3){
                ktw[co*8 + tid] = t;
                if (tid == 0) eRw[co*EDG + RKTHREADS] = t;   // k(1025)
            }
            if (tid < 3) acct[co] = fmaf(aw, t, acct[co]);
        }
    }
    if (S < 3) __syncthreads();
}

// ---------------- fused 7-step RK4 kernel ----------------
// u lives in smem across steps; validity shrinks 4/side/step; final core [28,1004).

__global__ void __launch_bounds__(RKTHREADS, 2)
rk4_fused(const float* __restrict__ src, float* __restrict__ dst,
          const float* __restrict__ t_span)
{
    extern __shared__ float sm[];
    float* s_su = sm;                      // CH*EXT
    float* s_eL = s_su + CH*EXT;           // 2*CH*EDG
    float* s_eR = s_eL + 2*CH*EDG;         // 2*CH*EDG
    float* s_kt = s_eR + 2*CH*EDG;         // 2*CH*8
    float* s_ts = s_kt + 2*CH*8;           // TSTEPS

    const int b    = blockIdx.y;
    const int bx   = blockIdx.x;
    const int gofs = bx*CORE - HALO7;
    const int tid  = threadIdx.x;
    const bool edge = (bx == 0) | (bx == gridDim.x - 1);

    if (tid < CH){
        s_eL[tid*EDG + 0] = 0.f;  s_eL[(CH+tid)*EDG + 0] = 0.f;   // k(0) sentinels
        s_kt[tid*8 + 6] = 0.f;    s_kt[tid*8 + 7] = 0.f;          // k(1031+) sentinels
        s_kt[(CH+tid)*8 + 6] = 0.f; s_kt[(CH+tid)*8 + 7] = 0.f;
    }
    if (tid < TSTEPS) s_ts[tid] = t_span[tid];
    #pragma unroll
    for (int ch=0; ch<CH; ch++){
        const float* sc = src + ((size_t)b*CH + ch)*NPT;
        for (int p=tid; p<EXT; p+=RKTHREADS){
            int g = gofs + p;
            s_su[ch*EXT + p] = ((unsigned)g < NPT) ? sc[g] : 0.f;
        }
    }
    __syncthreads();

    float* eL0 = s_eL;  float* eL1 = s_eL + CH*EDG;
    float* eR0 = s_eR;  float* eR1 = s_eR + CH*EDG;
    float* kt0 = s_kt;  float* kt1 = s_kt + CH*8;

    const int p0 = 4*tid;

    #pragma unroll 1
    for (int s=0; s<TSTEPS-1; s++){
        const float dt  = s_ts[s+1] - s_ts[s];
        const float hdt = 0.5f*dt;

        float cu[CH][4], kr[CH][4], acc[CH][4], acct[CH];
        #pragma unroll
        for (int co=0; co<CH; co++){
            acct[co]=0.f;
            acc[co][0]=0.f; acc[co][1]=0.f; acc[co][2]=0.f; acc[co][3]=0.f;
        }

        stage<0>(cu, eL0,eR0,kt0, eL0,eR0,kt0, s_su, 0.f, 1.f, gofs, tid, edge, kr, acc, acct);
        stage<1>(cu, eL0,eR0,kt0, eL1,eR1,kt1, s_su, hdt, 2.f, gofs, tid, edge, kr, acc, acct);
        stage<2>(cu, eL1,eR1,kt1, eL0,eR0,kt0, s_su, hdt, 2.f, gofs, tid, edge, kr, acc, acct);
        stage<3>(cu, eL0,eR0,kt0, eL1,eR1,kt1, s_su, dt,  1.f, gofs, tid, edge, kr, acc, acct);

        __syncthreads();            // stage-3 reads of su/edges complete

        const float dt6 = dt * (1.0f/6.0f);
        #pragma unroll
        for (int co=0; co<CH; co++){
            float* rp = s_su + co*EXT + p0;
            #pragma unroll
            for (int j=0; j<4; j++){
                int g = gofs + p0 + 1 + j;
                if (!edge || (unsigned)g < NPT)
                    rp[1+j] += dt6 * acc[co][j];
            }
        }
        if (tid < 3){
            int p = 1025 + tid;
            int g = gofs + p;
            if (!edge || (unsigned)g < NPT){
                #pragma unroll
                for (int co=0; co<CH; co++)
                    s_su[co*EXT + p] += dt6 * acct[co];
            }
        }
        __syncthreads();            // updated su visible to next step
    }

    // final store: core [28, 1004)
    #pragma unroll
    for (int co=0; co<CH; co++){
        float* dp = dst + ((size_t)b*CH + co)*NPT;
        const float* rp = s_su + co*EXT;
        #pragma unroll
        for (int j=0; j<4; j++){
            int p = p0 + 1 + j;
            int g = gofs + p;
            if (p >= HALO7 && p < EXT-HALO7 && (unsigned)g < NPT)
                dp[g] = rp[p];
        }
    }
}

// ---------------- forward 16-mode DFT (partial sums) ----------------
__global__ void __launch_bounds__(256)
fwd_dft_kernel(const float* __restrict__ u)
{
    const int blk  = blockIdx.x;                 // [0, BB*CH*FBLK)
    const int seg  = blk & (FBLK-1);
    const int bi   = blk / FBLK;                 // b*CH + i
    const int tid  = threadIdx.x;
    const int lane = tid & 31, warp = tid >> 5;
    const int n0   = seg*8192 + warp*1024 + lane;  // stride-32 walk, coalesced
    const float* x = u + (size_t)bi*NPT;

    const float TWO_PI = 6.283185307179586f;
    float cr[MODES], cim[MODES], ck[MODES], sk[MODES], dc[MODES], ds[MODES];
    #pragma unroll
    for (int k=0; k<MODES; k++){
        cr[k]=0.f; cim[k]=0.f;
        float a0 = TWO_PI * ((float)((k*n0) & NMASK) * (1.0f/NPT));
        sincosf(a0, &sk[k], &ck[k]);
        float ad = TWO_PI * ((float)(k*32) * (1.0f/NPT));
        sincosf(ad, &ds[k], &dc[k]);
    }
    #pragma unroll 2
    for (int j=0; j<32; j++){
        float v = __ldg(&x[n0 + (j<<5)]);
        #pragma unroll
        for (int k=0; k<MODES; k++){
            cr[k]  = fmaf( v, ck[k], cr[k]);     // X += u * e^{-i theta}
            cim[k] = fmaf(-v, sk[k], cim[k]);
            float nc = ck[k]*dc[k] - sk[k]*ds[k];
            sk[k] = fmaf(ck[k], ds[k], sk[k]*dc[k]);
            ck[k] = nc;
        }
    }
    #pragma unroll
    for (int k=0; k<MODES; k++){
        #pragma unroll
        for (int off=16; off; off>>=1){
            cr[k]  += __shfl_xor_sync(0xffffffffu, cr[k],  off);
            cim[k] += __shfl_xor_sync(0xffffffffu, cim[k], off);
        }
    }
    __shared__ float red[8][MODES*2];
    if (lane == 0){
        #pragma unroll
        for (int k=0; k<MODES; k++){
            red[warp][2*k]   = cr[k];
            red[warp][2*k+1] = cim[k];
        }
    }
    __syncthreads();
    if (tid < MODES*2){
        float s = 0.f;
        #pragma unroll
        for (int w=0; w<8; w++) s += red[w][tid];
        g_part[(bi*FBLK + seg)*(MODES*2) + tid] = s;
    }
}

// ---------------- mix: reduce partials, fold proj into mode weights ----------------
__global__ void mix_kernel(const float* __restrict__ sw_r, const float* __restrict__ sw_i,
                           const float* __restrict__ proj_w)
{
    const int b = blockIdx.x;
    const int t = threadIdx.x;         // 96 = CH*MODES
    const int o = t / MODES, k = t % MODES;
    float Zr = 0.f, Zi = 0.f;
    #pragma unroll
    for (int i=0; i<CH; i++){
        float Xr=0.f, Xi=0.f;
        int bi = b*CH + i;
        #pragma unroll
        for (int s=0; s<FBLK; s++){
            Xr += g_part[(bi*FBLK+s)*(MODES*2) + 2*k];
            Xi += g_part[(bi*FBLK+s)*(MODES*2) + 2*k + 1];
        }
        float Wr=0.f, Wi=0.f;
        #pragma unroll
        for (int c=0; c<CH; c++){
            float pw = proj_w[o*CH + c];
            Wr = fmaf(sw_r[(i*CH+c)*MODES + k], pw, Wr);
            Wi = fmaf(sw_i[(i*CH+c)*MODES + k], pw, Wi);
        }
        Zr += Xr*Wr - Xi*Wi;
        Zi += Xr*Wi + Xi*Wr;
    }
    float scale = (k==0) ? (1.0f/NPT) : (2.0f/NPT);   // irfft: DC once, others doubled
    g_Z[(b*CH+o)*MODES*2 + 2*k]     = Zr*scale;
    g_Z[(b*CH+o)*MODES*2 + 2*k + 1] = Zi*scale;
}

// ---------------- synthesis: 16-mode irfft + bias ----------------
__global__ void __launch_bounds__(256)
synth_kernel(float* __restrict__ out, const float* __restrict__ proj_b)
{
    const int blk  = blockIdx.x;        // b*8 + seg
    const int b    = blk >> 3, seg = blk & 7;
    const int tid  = threadIdx.x, lane = tid & 31, warp = tid >> 5;
    const int n0   = seg*8192 + warp*1024 + lane;

    __shared__ float zz[CH*MODES*2];
    __shared__ float pb[CH];
    if (tid < CH*MODES*2) zz[tid] = g_Z[b*CH*MODES*2 + tid];
    if (tid < CH)         pb[tid] = proj_b[tid];
    __syncthreads();

    const float TWO_PI = 6.283185307179586f;
    float ck[MODES], sk[MODES], dc[MODES], ds[MODES];
    #pragma unroll
    for (int k=0; k<MODES; k++){
        float a0 = TWO_PI * ((float)((k*n0) & NMASK) * (1.0f/NPT));
        sincosf(a0, &sk[k], &ck[k]);
        float ad = TWO_PI * ((float)(k*32) * (1.0f/NPT));
        sincosf(ad, &ds[k], &dc[k]);
    }
    for (int j=0; j<32; j++){
        int n = n0 + (j<<5);
        float accv[CH];
        #pragma unroll
        for (int o=0; o<CH; o++) accv[o] = pb[o];
        #pragma unroll
        for (int k=0; k<MODES; k++){
            float c = ck[k], s = sk[k];
            #pragma unroll
            for (int o=0; o<CH; o++){
                accv[o] = fmaf( zz[(o*MODES+k)*2],     c, accv[o]);
                accv[o] = fmaf(-zz[(o*MODES+k)*2 + 1], s, accv[o]);
            }
            float nc = c*dc[k] - s*ds[k];
            sk[k] = fmaf(c, ds[k], s*dc[k]);
            ck[k] = nc;
        }
        #pragma unroll
        for (int o=0; o<CH; o++)
            out[((size_t)(b*CH + o))*NPT + n] = accv[o];
    }
}

// ---------------- launch ----------------
extern "C" void kernel_launch(void* const* d_in, const int* in_sizes, int n_in,
                              void* d_out, int out_size)
{
    const float* u0     = (const float*)d_in[0];
    const float* t_span = (const float*)d_in[1];
    const float* conv_w = (const float*)d_in[2];
    const float* conv_b = (const float*)d_in[3];
    const float* sw_r   = (const float*)d_in[4];
    const float* sw_i   = (const float*)d_in[5];
    const float* proj_w = (const float*)d_in[6];
    const float* proj_b = (const float*)d_in[7];
    float* out = (float*)d_out;

    float* bufA = nullptr;
    cudaGetSymbolAddress((void**)&bufA, g_bufA);

    cudaMemcpyToSymbolAsync(c_w, conv_w, CH*CH*3*sizeof(float), 0,
                            cudaMemcpyDeviceToDevice, 0);
    cudaMemcpyToSymbolAsync(c_b, conv_b, CH*sizeof(float), 0,
                            cudaMemcpyDeviceToDevice, 0);

    const int rk_smem = (CH*EXT + 4*CH*EDG + 4*CH*8 + TSTEPS) * sizeof(float);
    cudaFuncSetAttribute(rk4_fused, cudaFuncAttributeMaxDynamicSharedMemorySize, rk_smem);

    dim3 rkgrid(NBLK, BB);
    rk4_fused<<<rkgrid, RKTHREADS, rk_smem>>>(u0, bufA, t_span);

    fwd_dft_kernel<<<BB*CH*FBLK, 256>>>(bufA);
    mix_kernel<<<BB, CH*MODES>>>(sw_r, sw_i, proj_w);
    synth_kernel<<<BB*8, 256>>>(out, proj_b);
}